// round 15
// baseline (speedup 1.0000x reference)
#include <cuda_runtime.h>
#include <mma.h>
#include <cstdint>

using namespace nvcuda;

// out[b,d,h,w] = (1/64) * sum_c left[b,c,h,w]*right[b,c,h,w-d], 0 for w<d
// B=8, C=64, H=160, W=320, D=48.
// tf32 banded Gram GEMM, wmma m16n16k8. fp32 staged via 3-deep cp.async pipeline,
// converted to tf32 IN SMEM once per chunk; fragments load with no per-element math.

#define HH  160
#define WW  320
#define DDn 48
#define HW  (HH * WW)
#define NT  320            // 10 warps, 1 i-tile (16 w) each
#define MW  160            // w-extent per CTA

#define LLD 168            // left stage row stride (floats), mult of 8
#define RLD 216            // right stage row stride (floats), mult of 8
#define SLD 68             // epilogue scratch row stride (floats)

// smem byte offsets: 3 buffers of left (16x168x4 = 10752 B) and right (16x216x4 = 13824 B)
#define SLB(i) ((i) * 10752)
#define SRB(i) (32256 + (i) * 13824)
#define SMEM_SZ 73728
#define SCR 0              // epilogue scratch overlays stages (43520 <= 73728)

static __device__ __forceinline__ uint32_t s2u(const void* p) {
    uint32_t a;
    asm("{ .reg .u64 t; cvta.to.shared.u64 t, %1; cvt.u32.u64 %0, t; }" : "=r"(a) : "l"(p));
    return a;
}
static __device__ __forceinline__ void cpasync16(void* dst, const void* src) {
    asm volatile("cp.async.cg.shared.global [%0], [%1], 16;"
                 :: "r"(s2u(dst)), "l"(src) : "memory");
}
static __device__ __forceinline__ float to_tf32(float x) {
    float y;
    asm("cvt.rna.tf32.f32 %0, %1;" : "=f"(y) : "f"(x));
    return y;
}

__global__ __launch_bounds__(NT, 2)
void corvol_tf32(const float* __restrict__ left,
                 const float* __restrict__ right,
                 float* __restrict__ out)
{
    extern __shared__ char sm[];

    const int bid  = blockIdx.x;
    const int half = bid & 1;
    const int bh   = bid >> 1;
    const int b    = bh / HH;
    const int h    = bh % HH;
    const int h0   = half * MW;
    const int tid  = threadIdx.x;
    const int wid  = tid >> 5;
    const int lid  = tid & 31;

    const float* lbase = left  + ((size_t)b * 64 * HH + h) * WW;
    const float* rbase = right + ((size_t)b * 64 * HH + h) * WW;

    // h0==0: zero right-stage cols [0,48) in all 3 buffers once; never overwritten
    // (w' < 0) -> stays zero -> w<d mask free (and cvt of 0 is 0).
    if (h0 == 0) {
        for (int i = tid; i < 3 * 16 * 12; i += NT) {
            const int bf = i / (16 * 12);
            const int r  = (i / 12) % 16;
            const int c  = (i % 12) * 4;
            float* st = (float*)(sm + SRB(bf));
            *(float4*)&st[r * RLD + c] = make_float4(0.f, 0.f, 0.f, 0.f);
        }
    }
    __syncthreads();

    auto issue_stage = [&](int kc) {
        const int bf = kc % 3;
        float* fL = (float*)(sm + SLB(bf));
        float* fR = (float*)(sm + SRB(bf));
        #pragma unroll
        for (int p = 0; p < 2; p++) {                 // left: 640 float4
            const int idx = tid + p * NT;
            const int rr = idx / 40, cc = (idx % 40) * 4;
            cpasync16(&fL[rr * LLD + cc],
                      lbase + (size_t)(16 * kc + rr) * HW + h0 + cc);
        }
        #pragma unroll
        for (int p = 0; p < 3; p++) {                 // right: 832 float4
            const int idx = tid + p * NT;
            if (idx < 16 * 52) {
                const int rr = idx / 52, cc = (idx % 52) * 4;
                const int wp = h0 - 48 + cc;
                if (wp >= 0)
                    cpasync16(&fR[rr * RLD + cc],
                              rbase + (size_t)(16 * kc + rr) * HW + wp);
            }
        }
        asm volatile("cp.async.commit_group;" ::: "memory");
    };

    issue_stage(0);
    issue_stage(1);

    wmma::fragment<wmma::accumulator, 16, 16, 8, float> acc[4];
    #pragma unroll
    for (int j = 0; j < 4; j++) wmma::fill_fragment(acc[j], 0.0f);

    for (int kc = 0; kc < 4; kc++) {
        const int bf = kc % 3;
        if (kc < 2) {
            asm volatile("cp.async.wait_group 1;" ::: "memory");
        } else {
            asm volatile("cp.async.wait_group 0;" ::: "memory");
        }
        __syncthreads();   // chunk kc landed; all warps done MMA-reading iter kc-1

        // Refill buffer (kc+2)%3 == (kc-1)%3 — released by the sync above.
        if (kc + 2 < 4) issue_stage(kc + 2);

        float* fL = (float*)(sm + SLB(bf));
        float* fR = (float*)(sm + SRB(bf));

        // In-place fp32 -> tf32 (RN) conversion, float4-vectorized.
        #pragma unroll
        for (int p = 0; p < 2; p++) {                 // left: 640 float4
            const int idx = tid + p * NT;
            const int rr = idx / 40, cc = (idx % 40) * 4;
            float4 v = *(float4*)&fL[rr * LLD + cc];
            v.x = to_tf32(v.x); v.y = to_tf32(v.y);
            v.z = to_tf32(v.z); v.w = to_tf32(v.w);
            *(float4*)&fL[rr * LLD + cc] = v;
        }
        #pragma unroll
        for (int p = 0; p < 3; p++) {                 // right: 832 float4
            const int idx = tid + p * NT;
            if (idx < 16 * 52) {
                const int rr = idx / 52, cc = (idx % 52) * 4;
                float4 v = *(float4*)&fR[rr * RLD + cc];
                v.x = to_tf32(v.x); v.y = to_tf32(v.y);
                v.z = to_tf32(v.z); v.w = to_tf32(v.w);
                *(float4*)&fR[rr * RLD + cc] = v;
            }
        }
        __syncthreads();   // converted data visible before fragment loads

        wmma::fragment<wmma::matrix_a, 16, 16, 8, wmma::precision::tf32,
                       wmma::col_major> a0, a1;
        wmma::load_matrix_sync(a0, fL + wid * 16, LLD);
        wmma::load_matrix_sync(a1, fL + 8 * LLD + wid * 16, LLD);

        #pragma unroll
        for (int j = 0; j < 4; j++) {
            wmma::fragment<wmma::matrix_b, 16, 16, 8, wmma::precision::tf32,
                           wmma::row_major> b0, b1;
            wmma::load_matrix_sync(b0, fR + wid * 16 + 16 * j, RLD);
            wmma::load_matrix_sync(b1, fR + 8 * RLD + wid * 16 + 16 * j, RLD);
            wmma::mma_sync(acc[j], a0, b0, acc[j]);
            wmma::mma_sync(acc[j], a1, b1, acc[j]);
        }
    }

    // Epilogue scratch overlays the fp32 stages other warps were reading: sync first.
    __syncthreads();

    float* scr = (float*)(sm + SCR) + wid * 16 * SLD;
    #pragma unroll
    for (int j = 0; j < 4; j++)
        wmma::store_matrix_sync(scr + 16 * j, acc[j], SLD, wmma::mem_row_major);
    __syncwarp();

    // out[d][wg] = D[i][wg-d]/64; scratch col = i + 48 - d
    {
        const int i    = lid & 15;
        const int dpar = lid >> 4;
        const int wg   = h0 + wid * 16 + i;
        float* ob = out + ((size_t)b * DDn * HH + h) * WW + wg;
        #pragma unroll
        for (int dd = 0; dd < 24; dd++) {
            const int d = 2 * dd + dpar;
            ob[(size_t)d * HW] = scr[i * SLD + (i + 48 - d)] * 0.015625f;
        }
    }
}

extern "C" void kernel_launch(void* const* d_in, const int* in_sizes, int n_in,
                              void* d_out, int out_size)
{
    cudaFuncSetAttribute(corvol_tf32, cudaFuncAttributeMaxDynamicSharedMemorySize, SMEM_SZ);
    corvol_tf32<<<8 * HH * 2, NT, SMEM_SZ>>>((const float*)d_in[0],
                                             (const float*)d_in[1],
                                             (float*)d_out);
}

// round 16
// speedup vs baseline: 1.0452x; 1.0452x over previous
#include <cuda_runtime.h>
#include <mma.h>
#include <cstdint>

using namespace nvcuda;

// out[b,d,h,w] = (1/64) * sum_c left[b,c,h,w]*right[b,c,h,w-d], 0 for w<d
// B=8, C=64, H=160, W=320, D=48.
// tf32 banded Gram GEMM, wmma m16n16k8. CTA = one (b,h) row; 10 warps,
// each warp computes 2 adjacent 16-w i-tiles sharing 5 B tiles per k-chunk.

#define HH  160
#define WW  320
#define DDn 48
#define HW  (HH * WW)
#define NT  320            // 10 warps x 2 i-tiles = 20 i-tiles = 320 w
#define NCH 8              // k-chunks of 8 channels

#define LLD 328            // left stage row stride (floats), mult of 8
#define RLD 376            // right stage row stride (floats), mult of 8
#define SLD 68             // epilogue scratch row stride (floats)

// 3 buffers: left 8x328x4 = 10496 B, right 8x376x4 = 12032 B
#define SLB(i) ((i) * 10496)
#define SRB(i) (31488 + (i) * 12032)
#define SMEM_SZ 67584
#define SCR 0              // per-warp scratch overlays stages: 10*4352 = 43520 <= 67584

static __device__ __forceinline__ uint32_t s2u(const void* p) {
    uint32_t a;
    asm("{ .reg .u64 t; cvta.to.shared.u64 t, %1; cvt.u32.u64 %0, t; }" : "=r"(a) : "l"(p));
    return a;
}
static __device__ __forceinline__ void cpasync16(void* dst, const void* src) {
    asm volatile("cp.async.cg.shared.global [%0], [%1], 16;"
                 :: "r"(s2u(dst)), "l"(src) : "memory");
}

__global__ __launch_bounds__(NT, 2)
void corvol_tf32(const float* __restrict__ left,
                 const float* __restrict__ right,
                 float* __restrict__ out)
{
    extern __shared__ char sm[];

    const int bid = blockIdx.x;
    const int b   = bid / HH;
    const int h   = bid % HH;
    const int tid = threadIdx.x;
    const int wid = tid >> 5;
    const int lid = tid & 31;

    const float* lbase = left  + ((size_t)b * 64 * HH + h) * WW;
    const float* rbase = right + ((size_t)b * 64 * HH + h) * WW;

    // Zero right-stage cols [0,48) (w' < 0) in all 3 buffers once; they are never
    // cp.async-overwritten -> stay zero -> w<d mask is free.
    for (int i = tid; i < 3 * 8 * 12; i += NT) {
        const int bf = i / 96;
        const int r  = (i / 12) % 8;
        const int c  = (i % 12) * 4;
        float* st = (float*)(sm + SRB(bf));
        *(float4*)&st[r * RLD + c] = make_float4(0.f, 0.f, 0.f, 0.f);
    }
    __syncthreads();

    // stage chunk kc (channels 8kc..8kc+7) into buffer kc % 3
    auto issue_stage = [&](int kc) {
        const int bf = kc % 3;
        float* fL = (float*)(sm + SLB(bf));
        float* fR = (float*)(sm + SRB(bf));
        // left: 8 rows x 80 float4 = 640 (2 per thread)
        #pragma unroll
        for (int p = 0; p < 2; p++) {
            const int idx = tid + p * NT;
            const int rr = idx / 80, cc = (idx % 80) * 4;
            cpasync16(&fL[rr * LLD + cc],
                      lbase + (size_t)(8 * kc + rr) * HW + cc);
        }
        // right: 8 rows x 92 float4 = 736; stage col c covers w' = c - 48
        #pragma unroll
        for (int p = 0; p < 3; p++) {
            const int idx = tid + p * NT;
            if (idx < 8 * 92) {
                const int rr = idx / 92, cc = (idx % 92) * 4;
                const int wp = cc - 48;
                if (wp >= 0)
                    cpasync16(&fR[rr * RLD + cc],
                              rbase + (size_t)(8 * kc + rr) * HW + wp);
            }
        }
        asm volatile("cp.async.commit_group;" ::: "memory");
    };

    issue_stage(0);
    issue_stage(1);

    // acc[s][j]: i-tile (2*wid + s), n-tile j. D-tile cols: w' from (i0 - 48 + 16j).
    wmma::fragment<wmma::accumulator, 16, 16, 8, float> acc[2][4];
    #pragma unroll
    for (int s = 0; s < 2; s++)
        #pragma unroll
        for (int j = 0; j < 4; j++) wmma::fill_fragment(acc[s][j], 0.0f);

    for (int kc = 0; kc < NCH; kc++) {
        const int bf = kc % 3;
        if (kc < NCH - 2) {
            asm volatile("cp.async.wait_group 1;" ::: "memory");
        } else {
            asm volatile("cp.async.wait_group 0;" ::: "memory");
        }
        __syncthreads();   // chunk kc landed; all warps done MMA-reading iter kc-1

        if (kc + 2 < NCH) issue_stage(kc + 2);  // refill (kc+2)%3 == (kc-1)%3

        const float* fL = (const float*)(sm + SLB(bf));
        const float* fR = (const float*)(sm + SRB(bf));

        // A fragments (col_major 16x8): i-tile s at fL[k*LLD + 32*wid + 16*s + i]
        wmma::fragment<wmma::matrix_a, 16, 16, 8, wmma::precision::tf32,
                       wmma::col_major> a[2];
        #pragma unroll
        for (int s = 0; s < 2; s++) {
            wmma::load_matrix_sync(a[s], fL + 32 * wid + 16 * s, LLD);
            #pragma unroll
            for (int t = 0; t < a[s].num_elements; t++)
                a[s].x[t] = wmma::__float_to_tf32(a[s].x[t]);
        }

        // B tiles t = 0..4 (row_major 8x16) at stage col 32*wid + 16*t,
        // shared by both i-tiles: (s, j) with t = s + j.
        #pragma unroll
        for (int t = 0; t < 5; t++) {
            wmma::fragment<wmma::matrix_b, 16, 16, 8, wmma::precision::tf32,
                           wmma::row_major> bt;
            wmma::load_matrix_sync(bt, fR + 32 * wid + 16 * t, RLD);
            #pragma unroll
            for (int e = 0; e < bt.num_elements; e++)
                bt.x[e] = wmma::__float_to_tf32(bt.x[e]);
            if (t < 4)  wmma::mma_sync(acc[0][t], a[0], bt, acc[0][t]);
            if (t >= 1) wmma::mma_sync(acc[1][t - 1], a[1], bt, acc[1][t - 1]);
        }
    }

    // Epilogue: per-warp scratch overlays stage buffers (all MMA reads done after sync).
    __syncthreads();
    float* scr = (float*)(sm + SCR) + wid * 16 * SLD;

    #pragma unroll
    for (int s = 0; s < 2; s++) {
        #pragma unroll
        for (int j = 0; j < 4; j++)
            wmma::store_matrix_sync(scr + 16 * j, acc[s][j], SLD, wmma::mem_row_major);
        __syncwarp();

        // D-tile row i (= lid&15), scratch col = i + 48 - d; out w = 32*wid + 16*s + i
        const int i    = lid & 15;
        const int dpar = lid >> 4;
        const int wg   = 32 * wid + 16 * s + i;
        float* ob = out + ((size_t)b * DDn * HH + h) * WW + wg;
        #pragma unroll
        for (int dd = 0; dd < 24; dd++) {
            const int d = 2 * dd + dpar;
            ob[(size_t)d * HW] = scr[i * SLD + (i + 48 - d)] * 0.015625f;
        }
        __syncwarp();   // wave s reads done before wave s+1 overwrites scratch
    }
}

extern "C" void kernel_launch(void* const* d_in, const int* in_sizes, int n_in,
                              void* d_out, int out_size)
{
    cudaFuncSetAttribute(corvol_tf32, cudaFuncAttributeMaxDynamicSharedMemorySize, SMEM_SZ);
    corvol_tf32<<<8 * HH, NT, SMEM_SZ>>>((const float*)d_in[0],
                                         (const float*)d_in[1],
                                         (float*)d_out);
}